// round 2
// baseline (speedup 1.0000x reference)
#include <cuda_runtime.h>
#include <stdint.h>

#define VOCAB   1825324
#define BS      4096
#define D       128
#define SEQ     20
#define UNZ     20480            // BS + NNEG unique labels
#define NWORDS  57042            // ceil(VOCAB/32)
#define NSCANBLK 56              // ceil(NWORDS/1024)

// ---------------- device scratch (static; no allocations) ----------------
__device__ unsigned int g_bitmap[NWORDS];
__device__ int   g_wordpref[NWORDS];     // exclusive prefix of popcounts
__device__ int   g_bsum[NSCANBLK];
__device__ int   g_bsum_scan[NSCANBLK];
__device__ int   g_posidx[BS];
__device__ int   g_sorted[UNZ];
__device__ float g_bias[UNZ];            // (-icf*log(p+1e-11))/temp, sorted order
__device__ float g_Xt[D * BS];           // x transposed, k-major  [k][b]
__device__ float g_Eg[D * UNZ];          // gathered emb, k-major  [k][c]

__device__ __forceinline__ int clampv(int v) {
    return v < 0 ? 0 : (v >= VOCAB ? VOCAB - 1 : v);
}

// ---------------- ranking structure ----------------
__global__ void k_zero_bitmap() {
    int i = blockIdx.x * blockDim.x + threadIdx.x;
    if (i < NWORDS) g_bitmap[i] = 0u;
}

__global__ void k_setbits(const int* __restrict__ labels,
                          const int* __restrict__ uneg) {
    int i = blockIdx.x * blockDim.x + threadIdx.x;
    if (i >= UNZ) return;
    int v = clampv(i < BS ? labels[i] : uneg[i - BS]);
    atomicOr(&g_bitmap[v >> 5], 1u << (v & 31));
}

__global__ void k_blocksums() {
    __shared__ int red[8];
    int base = blockIdx.x * 1024 + threadIdx.x * 4;
    int s = 0;
#pragma unroll
    for (int j = 0; j < 4; j++) {
        int w = base + j;
        if (w < NWORDS) s += __popc(g_bitmap[w]);
    }
    for (int o = 16; o; o >>= 1) s += __shfl_down_sync(0xffffffffu, s, o);
    if ((threadIdx.x & 31) == 0) red[threadIdx.x >> 5] = s;
    __syncthreads();
    if (threadIdx.x == 0) {
        int t = 0;
        for (int w = 0; w < 8; w++) t += red[w];
        g_bsum[blockIdx.x] = t;
    }
}

__global__ void k_scan_bsum() {
    if (threadIdx.x == 0) {
        int acc = 0;
        for (int i = 0; i < NSCANBLK; i++) { g_bsum_scan[i] = acc; acc += g_bsum[i]; }
    }
}

__global__ void k_wordpref() {
    __shared__ int warpsum[8];
    int t = threadIdx.x;
    int base = blockIdx.x * 1024 + t * 4;
    int c[4]; int s = 0;
#pragma unroll
    for (int j = 0; j < 4; j++) {
        int w = base + j;
        c[j] = (w < NWORDS) ? __popc(g_bitmap[w]) : 0;
        s += c[j];
    }
    int lane = t & 31, wid = t >> 5;
    int incl = s;
    for (int o = 1; o < 32; o <<= 1) {
        int x = __shfl_up_sync(0xffffffffu, incl, o);
        if (lane >= o) incl += x;
    }
    if (lane == 31) warpsum[wid] = incl;
    __syncthreads();
    if (wid == 0 && lane < 8) {
        int v = warpsum[lane];
        int iv = v;
        for (int o = 1; o < 8; o <<= 1) {
            int x = __shfl_up_sync(0xffu, iv, o);
            if (lane >= o) iv += x;
        }
        warpsum[lane] = iv - v;  // exclusive
    }
    __syncthreads();
    int start = g_bsum_scan[blockIdx.x] + warpsum[wid] + (incl - s);
#pragma unroll
    for (int j = 0; j < 4; j++) {
        int w = base + j;
        if (w < NWORDS) g_wordpref[w] = start;
        start += c[j];
    }
}

__device__ __forceinline__ int rank_of(int v) {
    unsigned int w = g_bitmap[v >> 5];
    return g_wordpref[v >> 5] + __popc(w & ((1u << (v & 31)) - 1u));
}

// sorted scatter + pos_idx + bias (already divided by temperature)
__global__ void k_scatter(const int* __restrict__ labels,
                          const int* __restrict__ uneg,
                          const float* __restrict__ probs,
                          const float* __restrict__ temp,
                          const float* __restrict__ icf) {
    int i = blockIdx.x * blockDim.x + threadIdx.x;
    if (i >= UNZ) return;
    int v = clampv(i < BS ? labels[i] : uneg[i - BS]);
    int r = rank_of(v);
    if (r < 0) r = 0; if (r >= UNZ) r = UNZ - 1;
    g_sorted[r] = v;
    if (i < BS) g_posidx[i] = r;
    g_bias[r] = (-icf[0] * logf(probs[v] + 1e-11f)) / temp[0];
}

// gather emb rows in sorted order, store k-major (transposed) via smem
__global__ void k_gatherE(const float* __restrict__ emb) {
    __shared__ float tile[32][129];
    int c0 = blockIdx.x * 32;
    for (int id = threadIdx.x; id < 32 * 128; id += blockDim.x) {
        int cc = id >> 7, k = id & 127;
        int v = g_sorted[c0 + cc];
        tile[cc][k] = emb[(size_t)v * D + k];
    }
    __syncthreads();
    for (int id = threadIdx.x; id < 32 * 128; id += blockDim.x) {
        int k = id >> 5, cc = id & 31;
        g_Eg[k * UNZ + c0 + cc] = tile[cc][k];
    }
}

__global__ void k_transposeX(const float* __restrict__ x) {
    __shared__ float tile[32][129];
    int r0 = blockIdx.x * 32;
    for (int id = threadIdx.x; id < 32 * 128; id += blockDim.x) {
        int rr = id >> 7, k = id & 127;
        tile[rr][k] = x[(r0 + rr) * D + k];
    }
    __syncthreads();
    for (int id = threadIdx.x; id < 32 * 128; id += blockDim.x) {
        int k = id >> 5, rr = id & 31;
        g_Xt[k * BS + r0 + rr] = tile[rr][k];
    }
}

// ---------------- GEMM + fused epilogue ----------------
#define BM 64
#define BN 128
#define BK 64

__global__ __launch_bounds__(256) void k_gemm(float* __restrict__ out,
                                              const float* __restrict__ temp) {
    __shared__ float Xs[BK][BM];   // 16 KB
    __shared__ float Es[BK][BN];   // 32 KB
    int bn0 = blockIdx.x * BN;
    int bm0 = blockIdx.y * BM;
    int t = threadIdx.x;
    int tm = t >> 4, tn = t & 15;   // 16x16 thread grid, 4x8 micro-tile

    float acc[4][8];
#pragma unroll
    for (int i = 0; i < 4; i++)
#pragma unroll
        for (int j = 0; j < 8; j++) acc[i][j] = 0.f;

    for (int kt = 0; kt < D; kt += BK) {
#pragma unroll
        for (int i = 0; i < 4; i++) {          // Xs: 1024 float4
            int id4 = t + i * 256;
            int kk = id4 >> 4, m4 = id4 & 15;
            *(float4*)&Xs[kk][m4 * 4] =
                *(const float4*)&g_Xt[(kt + kk) * BS + bm0 + m4 * 4];
        }
#pragma unroll
        for (int i = 0; i < 8; i++) {          // Es: 2048 float4
            int id4 = t + i * 256;
            int kk = id4 >> 5, n4 = id4 & 31;
            *(float4*)&Es[kk][n4 * 4] =
                *(const float4*)&g_Eg[(kt + kk) * UNZ + bn0 + n4 * 4];
        }
        __syncthreads();
#pragma unroll
        for (int kk = 0; kk < BK; kk++) {
            float4 xf = *(float4*)&Xs[kk][tm * 4];
            float4 e0 = *(float4*)&Es[kk][tn * 8];
            float4 e1 = *(float4*)&Es[kk][tn * 8 + 4];
            float xv[4] = {xf.x, xf.y, xf.z, xf.w};
            float ev[8] = {e0.x, e0.y, e0.z, e0.w, e1.x, e1.y, e1.z, e1.w};
#pragma unroll
            for (int i = 0; i < 4; i++)
#pragma unroll
                for (int j = 0; j < 8; j++)
                    acc[i][j] = fmaf(xv[i], ev[j], acc[i][j]);
        }
        __syncthreads();
    }

    float invt = 1.0f / temp[0];
    int pos[4];
#pragma unroll
    for (int i = 0; i < 4; i++) pos[i] = g_posidx[bm0 + tm * 4 + i];
    float bias[8];
#pragma unroll
    for (int j = 0; j < 8; j++) bias[j] = g_bias[bn0 + tn * 8 + j];

#pragma unroll
    for (int i = 0; i < 4; i++) {
        int b = bm0 + tm * 4 + i;
        size_t rowoff = (size_t)b * UNZ;
#pragma unroll
        for (int j = 0; j < 8; j++) {
            int c = bn0 + tn * 8 + j;
            float val = fmaf(acc[i][j], invt, bias[j]);
            int dest = (c == pos[i]) ? 0 : (c < pos[i] ? c + 1 : c);
            out[rowoff + dest] = val;
        }
    }
}

// mask: scatter zeros for item_seq hits (excluding the positive column)
__global__ void k_mask(const int* __restrict__ item_seq,
                       float* __restrict__ out) {
    int i = blockIdx.x * blockDim.x + threadIdx.x;
    if (i >= BS * SEQ) return;
    int b = i / SEQ;
    int tkn = item_seq[i];
    if (tkn < 0 || tkn >= VOCAB) return;
    unsigned int w = g_bitmap[tkn >> 5];
    if (!(w & (1u << (tkn & 31)))) return;
    int c = g_wordpref[tkn >> 5] + __popc(w & ((1u << (tkn & 31)) - 1u));
    int pos = g_posidx[b];
    if (c == pos) return;
    int dest = (c < pos) ? c + 1 : c;
    out[(size_t)b * UNZ + dest] = 0.0f;
}

__global__ void k_zerotail(float* out, size_t start, size_t n) {
    size_t i = (size_t)blockIdx.x * blockDim.x + threadIdx.x;
    if (i < n) out[start + i] = 0.f;
}

// ---------------- launch ----------------
extern "C" void kernel_launch(void* const* d_in, const int* in_sizes, int n_in,
                              void* d_out, int out_size) {
    const float* x      = (const float*)d_in[0];
    const int*   labels = (const int*)d_in[1];
    const int*   iseq   = (const int*)d_in[2];
    const float* probs  = (const float*)d_in[3];
    const int*   uneg   = (const int*)d_in[4];
    const float* emb    = (const float*)d_in[5];
    const float* temp   = (const float*)d_in[6];
    const float* icf    = (const float*)d_in[7];
    float* out = (float*)d_out;

    k_zero_bitmap<<<(NWORDS + 255) / 256, 256>>>();
    k_setbits<<<(UNZ + 255) / 256, 256>>>(labels, uneg);
    k_blocksums<<<NSCANBLK, 256>>>();
    k_scan_bsum<<<1, 32>>>();
    k_wordpref<<<NSCANBLK, 256>>>();
    k_scatter<<<(UNZ + 255) / 256, 256>>>(labels, uneg, probs, temp, icf);
    k_gatherE<<<UNZ / 32, 256>>>(emb);
    k_transposeX<<<BS / 32, 256>>>(x);

    dim3 gg(UNZ / BN, BS / BM);
    k_gemm<<<gg, 256>>>(out, temp);

    k_mask<<<(BS * SEQ + 255) / 256, 256>>>(iseq, out);

    size_t main_n = (size_t)BS * UNZ;
    if ((size_t)out_size > main_n) {
        size_t tail = (size_t)out_size - main_n;
        k_zerotail<<<(unsigned)((tail + 255) / 256), 256>>>(out, main_n, tail);
    }
}

// round 4
// speedup vs baseline: 5.9698x; 5.9698x over previous
#include <cuda_runtime.h>
#include <cuda_bf16.h>
#include <stdint.h>

#define VOCAB   1825324
#define BS      4096
#define D       128
#define SEQ     20
#define UNZ     20480
#define NWORDS  57042
#define NSCANBLK 56

// ---------------- device scratch ----------------
__device__ unsigned int g_bitmap[NWORDS];
__device__ int   g_wordpref[NWORDS];
__device__ int   g_bsum[NSCANBLK];
__device__ int   g_bsum_scan[NSCANBLK];
__device__ int   g_posidx[BS];
__device__ int   g_sorted[UNZ];
__device__ float g_bias[UNZ];            // (-icf*log(p+1e-11))/temp, sorted order
__device__ __nv_bfloat16 g_Xb[BS * D];   // x bf16, row-major [b][k]
__device__ __nv_bfloat16 g_Ebs[UNZ * D]; // sorted emb bf16, row-major [c][k]

__device__ __forceinline__ int clampv(int v) {
    return v < 0 ? 0 : (v >= VOCAB ? VOCAB - 1 : v);
}

__device__ __forceinline__ uint32_t smem_u32(const void* p) {
    uint32_t a;
    asm("{ .reg .u64 t; cvta.to.shared.u64 t, %1; cvt.u32.u64 %0, t; }" : "=r"(a) : "l"(p));
    return a;
}

// ---------------- ranking structure ----------------
__global__ void k_zero_bitmap() {
    int i = blockIdx.x * blockDim.x + threadIdx.x;
    if (i < NWORDS) g_bitmap[i] = 0u;
}

__global__ void k_setbits(const int* __restrict__ labels,
                          const int* __restrict__ uneg) {
    int i = blockIdx.x * blockDim.x + threadIdx.x;
    if (i >= UNZ) return;
    int v = clampv(i < BS ? labels[i] : uneg[i - BS]);
    atomicOr(&g_bitmap[v >> 5], 1u << (v & 31));
}

__global__ void k_blocksums() {
    __shared__ int red[8];
    int base = blockIdx.x * 1024 + threadIdx.x * 4;
    int s = 0;
#pragma unroll
    for (int j = 0; j < 4; j++) {
        int w = base + j;
        if (w < NWORDS) s += __popc(g_bitmap[w]);
    }
    for (int o = 16; o; o >>= 1) s += __shfl_down_sync(0xffffffffu, s, o);
    if ((threadIdx.x & 31) == 0) red[threadIdx.x >> 5] = s;
    __syncthreads();
    if (threadIdx.x == 0) {
        int t = 0;
        for (int w = 0; w < 8; w++) t += red[w];
        g_bsum[blockIdx.x] = t;
    }
}

__global__ void k_scan_bsum() {
    if (threadIdx.x == 0) {
        int acc = 0;
        for (int i = 0; i < NSCANBLK; i++) { g_bsum_scan[i] = acc; acc += g_bsum[i]; }
    }
}

__global__ void k_wordpref() {
    __shared__ int warpsum[8];
    int t = threadIdx.x;
    int base = blockIdx.x * 1024 + t * 4;
    int c[4]; int s = 0;
#pragma unroll
    for (int j = 0; j < 4; j++) {
        int w = base + j;
        c[j] = (w < NWORDS) ? __popc(g_bitmap[w]) : 0;
        s += c[j];
    }
    int lane = t & 31, wid = t >> 5;
    int incl = s;
    for (int o = 1; o < 32; o <<= 1) {
        int x = __shfl_up_sync(0xffffffffu, incl, o);
        if (lane >= o) incl += x;
    }
    if (lane == 31) warpsum[wid] = incl;
    __syncthreads();
    if (wid == 0 && lane < 8) {
        int v = warpsum[lane];
        int iv = v;
        for (int o = 1; o < 8; o <<= 1) {
            int x = __shfl_up_sync(0xffu, iv, o);
            if (lane >= o) iv += x;
        }
        warpsum[lane] = iv - v;
    }
    __syncthreads();
    int start = g_bsum_scan[blockIdx.x] + warpsum[wid] + (incl - s);
#pragma unroll
    for (int j = 0; j < 4; j++) {
        int w = base + j;
        if (w < NWORDS) g_wordpref[w] = start;
        start += c[j];
    }
}

__device__ __forceinline__ int rank_of(int v) {
    unsigned int w = g_bitmap[v >> 5];
    return g_wordpref[v >> 5] + __popc(w & ((1u << (v & 31)) - 1u));
}

__global__ void k_scatter(const int* __restrict__ labels,
                          const int* __restrict__ uneg,
                          const float* __restrict__ probs,
                          const float* __restrict__ temp,
                          const float* __restrict__ icf) {
    int i = blockIdx.x * blockDim.x + threadIdx.x;
    if (i >= UNZ) return;
    int v = clampv(i < BS ? labels[i] : uneg[i - BS]);
    int r = rank_of(v);
    if (r < 0) r = 0;
    if (r >= UNZ) r = UNZ - 1;
    g_sorted[r] = v;
    if (i < BS) g_posidx[i] = r;
    g_bias[r] = (-icf[0] * logf(probs[v] + 1e-11f)) / temp[0];
}

// ---------------- bf16 prep ----------------
__device__ __forceinline__ uint32_t pack_bf16x2(float lo, float hi) {
    uint32_t l = (uint32_t)__bfloat16_as_ushort(__float2bfloat16_rn(lo));
    uint32_t h = (uint32_t)__bfloat16_as_ushort(__float2bfloat16_rn(hi));
    return (h << 16) | l;
}

__global__ void k_prepX(const float* __restrict__ x) {
    int i4 = blockIdx.x * blockDim.x + threadIdx.x;
    if (i4 >= BS * D / 4) return;
    float4 v = ((const float4*)x)[i4];
    uint2 o;
    o.x = pack_bf16x2(v.x, v.y);
    o.y = pack_bf16x2(v.z, v.w);
    ((uint2*)g_Xb)[i4] = o;
}

__global__ void k_gatherEb(const float* __restrict__ emb) {
    int row = blockIdx.x * 8 + (threadIdx.x >> 5);
    int lane = threadIdx.x & 31;
    if (row >= UNZ) return;
    int v = g_sorted[row];
    float4 f = ((const float4*)(emb + (size_t)v * D))[lane];
    uint2 o;
    o.x = pack_bf16x2(f.x, f.y);
    o.y = pack_bf16x2(f.z, f.w);
    ((uint2*)g_Ebs)[(size_t)row * 32 + lane] = o;
}

// ---------------- HMMA GEMM + fused epilogue ----------------
// CTA tile 128(M) x 128(N), K = 128 whole.
// SMEM: A [128][272B], B [128][272B]; epilogue fp32 [128][132] reuses A+B region.
#define ROWB   272                       // padded row stride in bytes (136 bf16)
#define A_OFF  0
#define B_OFF  (128 * ROWB)              // 34816
#define EPI_STRIDE 132
#define BIAS_OFF (2 * 128 * ROWB)        // 69632
#define POS_OFF  (BIAS_OFF + 512)
#define SMEM_TOT (POS_OFF + 512)         // 70656 bytes

__device__ __forceinline__ void ldsm_x4(uint32_t addr, uint32_t& r0, uint32_t& r1,
                                        uint32_t& r2, uint32_t& r3) {
    asm volatile("ldmatrix.sync.aligned.m8n8.x4.shared.b16 {%0,%1,%2,%3}, [%4];"
                 : "=r"(r0), "=r"(r1), "=r"(r2), "=r"(r3) : "r"(addr));
}

__device__ __forceinline__ void mma16816(float* c, uint32_t a0, uint32_t a1,
                                         uint32_t a2, uint32_t a3,
                                         uint32_t b0, uint32_t b1) {
    asm volatile("mma.sync.aligned.m16n8k16.row.col.f32.bf16.bf16.f32 "
                 "{%0,%1,%2,%3}, {%4,%5,%6,%7}, {%8,%9}, {%0,%1,%2,%3};"
                 : "+f"(c[0]), "+f"(c[1]), "+f"(c[2]), "+f"(c[3])
                 : "r"(a0), "r"(a1), "r"(a2), "r"(a3), "r"(b0), "r"(b1));
}

__global__ __launch_bounds__(256) void k_gemm_mma(float* __restrict__ out,
                                                  const float* __restrict__ temp) {
    extern __shared__ char sm[];
    uint32_t smb = smem_u32(sm);
    int tid = threadIdx.x;
    int w = tid >> 5, lane = tid & 31;
    int wm = w >> 2, wn = w & 3;           // warp tile: rows wm*64, cols wn*32
    int N0 = blockIdx.x * 128;
    int M0 = blockIdx.y * 128;

    // ---- stage A, B tiles (uint4, padded rows) ----
    const uint4* Asrc = (const uint4*)g_Xb;
    const uint4* Bsrc = (const uint4*)g_Ebs;
#pragma unroll
    for (int it = 0; it < 8; it++) {
        int id = tid + it * 256;            // 2048 chunks each
        int row = id >> 4, q = id & 15;
        *(uint4*)(sm + A_OFF + row * ROWB + q * 16) = Asrc[(size_t)(M0 + row) * 16 + q];
        *(uint4*)(sm + B_OFF + row * ROWB + q * 16) = Bsrc[(size_t)(N0 + row) * 16 + q];
    }
    // bias / pos staging (region does not overlap epilogue buffer)
    if (tid < 128) ((float*)(sm + BIAS_OFF))[tid] = g_bias[N0 + tid];
    else ((int*)(sm + POS_OFF))[tid - 128] = g_posidx[M0 + tid - 128];
    __syncthreads();

    float acc[4][4][4];
#pragma unroll
    for (int i = 0; i < 4; i++)
#pragma unroll
        for (int j = 0; j < 4; j++)
#pragma unroll
            for (int e = 0; e < 4; e++) acc[i][j][e] = 0.f;

    int sel = lane >> 3, r8 = lane & 7;
    // A x4 tile addressing: row = mi*16 + (sel&1)*8 + r8, kbyte = (sel>>1)*16
    uint32_t a_base = smb + A_OFF + (uint32_t)(wm * 64 + (sel & 1) * 8 + r8) * ROWB
                    + (uint32_t)((sel >> 1) * 16);
    // B x4 pair addressing: row = pair*16 + (sel>>1)*8 + r8, kbyte = (sel&1)*16
    uint32_t b_base = smb + B_OFF + (uint32_t)(wn * 32 + (sel >> 1) * 8 + r8) * ROWB
                    + (uint32_t)((sel & 1) * 16);

#pragma unroll
    for (int kk = 0; kk < 8; kk++) {
        uint32_t a[4][4];
#pragma unroll
        for (int mi = 0; mi < 4; mi++)
            ldsm_x4(a_base + (uint32_t)(mi * 16) * ROWB + kk * 32,
                    a[mi][0], a[mi][1], a[mi][2], a[mi][3]);
        uint32_t b[4][2];
#pragma unroll
        for (int p = 0; p < 2; p++) {
            uint32_t r0, r1, r2, r3;
            ldsm_x4(b_base + (uint32_t)(p * 16) * ROWB + kk * 32, r0, r1, r2, r3);
            b[p * 2][0] = r0; b[p * 2][1] = r1;       // n-tile p*2
            b[p * 2 + 1][0] = r2; b[p * 2 + 1][1] = r3; // n-tile p*2+1
        }
#pragma unroll
        for (int mi = 0; mi < 4; mi++)
#pragma unroll
            for (int nt = 0; nt < 4; nt++)
                mma16816(acc[mi][nt], a[mi][0], a[mi][1], a[mi][2], a[mi][3],
                         b[nt][0], b[nt][1]);
    }
    __syncthreads();   // done reading A/B smem; reuse region as epilogue buffer

    // ---- fragments -> smem (fp32, stride 132) ----
    float* epi = (float*)sm;
    int fr = lane >> 2, fc = (lane & 3) * 2;
#pragma unroll
    for (int mi = 0; mi < 4; mi++) {
#pragma unroll
        for (int nt = 0; nt < 4; nt++) {
            int r0 = wm * 64 + mi * 16 + fr;
            int c0 = wn * 32 + nt * 8 + fc;
            *(float2*)&epi[r0 * EPI_STRIDE + c0] = make_float2(acc[mi][nt][0], acc[mi][nt][1]);
            *(float2*)&epi[(r0 + 8) * EPI_STRIDE + c0] = make_float2(acc[mi][nt][2], acc[mi][nt][3]);
        }
    }
    __syncthreads();

    // ---- coalesced epilogue: bias + /temp + positive-column permutation ----
    const float* sbias = (const float*)(sm + BIAS_OFF);
    const int*   spos  = (const int*)(sm + POS_OFF);
    float invt = 1.0f / temp[0];
    int col = tid & 127;
    int rhalf = tid >> 7;                  // 0 or 1
    int c = N0 + col;
    float bc = sbias[col];
#pragma unroll 4
    for (int it = 0; it < 64; it++) {
        int row = it * 2 + rhalf;
        float val = fmaf(epi[row * EPI_STRIDE + col], invt, bc);
        int pr = spos[row];
        int dest = (c == pr) ? 0 : (c < pr ? c + 1 : c);
        out[(size_t)(M0 + row) * UNZ + dest] = val;
    }
}

// mask: scatter zeros for item_seq hits (excluding the positive column)
__global__ void k_mask(const int* __restrict__ item_seq,
                       float* __restrict__ out) {
    int i = blockIdx.x * blockDim.x + threadIdx.x;
    if (i >= BS * SEQ) return;
    int b = i / SEQ;
    int tkn = item_seq[i];
    if (tkn < 0 || tkn >= VOCAB) return;
    unsigned int w = g_bitmap[tkn >> 5];
    if (!(w & (1u << (tkn & 31)))) return;
    int c = g_wordpref[tkn >> 5] + __popc(w & ((1u << (tkn & 31)) - 1u));
    int pos = g_posidx[b];
    if (c == pos) return;
    int dest = (c < pos) ? c + 1 : c;
    out[(size_t)b * UNZ + dest] = 0.0f;
}

__global__ void k_zerotail(float* out, size_t start, size_t n) {
    size_t i = (size_t)blockIdx.x * blockDim.x + threadIdx.x;
    if (i < n) out[start + i] = 0.f;
}

// ---------------- launch ----------------
extern "C" void kernel_launch(void* const* d_in, const int* in_sizes, int n_in,
                              void* d_out, int out_size) {
    const float* x      = (const float*)d_in[0];
    const int*   labels = (const int*)d_in[1];
    const int*   iseq   = (const int*)d_in[2];
    const float* probs  = (const float*)d_in[3];
    const int*   uneg   = (const int*)d_in[4];
    const float* emb    = (const float*)d_in[5];
    const float* temp   = (const float*)d_in[6];
    const float* icf    = (const float*)d_in[7];
    float* out = (float*)d_out;

    cudaFuncSetAttribute(k_gemm_mma, cudaFuncAttributeMaxDynamicSharedMemorySize, SMEM_TOT);

    k_zero_bitmap<<<(NWORDS + 255) / 256, 256>>>();
    k_setbits<<<(UNZ + 255) / 256, 256>>>(labels, uneg);
    k_blocksums<<<NSCANBLK, 256>>>();
    k_scan_bsum<<<1, 32>>>();
    k_wordpref<<<NSCANBLK, 256>>>();
    k_scatter<<<(UNZ + 255) / 256, 256>>>(labels, uneg, probs, temp, icf);
    k_prepX<<<(BS * D / 4 + 255) / 256, 256>>>(x);
    k_gatherEb<<<UNZ / 8, 256>>>(emb);

    dim3 gg(UNZ / 128, BS / 128);
    k_gemm_mma<<<gg, 256, SMEM_TOT>>>(out, temp);

    k_mask<<<(BS * SEQ + 255) / 256, 256>>>(iseq, out);

    size_t main_n = (size_t)BS * UNZ;
    if ((size_t)out_size > main_n) {
        size_t tail = (size_t)out_size - main_n;
        k_zerotail<<<(unsigned)((tail + 255) / 256), 256>>>(out, main_n, tail);
    }
}

// round 5
// speedup vs baseline: 6.3998x; 1.0720x over previous
#include <cuda_runtime.h>
#include <cuda_bf16.h>
#include <stdint.h>

#define VOCAB   1825324
#define BS      4096
#define D       128
#define SEQ     20
#define UNZ     20480
#define NWORDS  57042
#define NSCANBLK 56

// ---------------- device scratch ----------------
__device__ unsigned int g_bitmap[NWORDS];
__device__ int   g_wordpref[NWORDS];
__device__ int   g_bsum[NSCANBLK];
__device__ int   g_posidx[BS];
__device__ int   g_sorted[UNZ];
__device__ float g_bias[UNZ];            // (-icf*log(p+1e-11))/temp, sorted order
__device__ __nv_bfloat16 g_Xb[BS * D];   // x bf16, row-major [b][k]
__device__ __nv_bfloat16 g_Ebs[UNZ * D]; // sorted emb bf16, row-major [c][k]

__device__ __forceinline__ int clampv(int v) {
    return v < 0 ? 0 : (v >= VOCAB ? VOCAB - 1 : v);
}

__device__ __forceinline__ uint32_t smem_u32(const void* p) {
    uint32_t a;
    asm("{ .reg .u64 t; cvta.to.shared.u64 t, %1; cvt.u32.u64 %0, t; }" : "=r"(a) : "l"(p));
    return a;
}

__device__ __forceinline__ void stcs(float* p, float v) {
    asm volatile("st.global.cs.f32 [%0], %1;" :: "l"(p), "f"(v));
}

__device__ __forceinline__ void cp_async16(uint32_t saddr, const void* gaddr) {
    asm volatile("cp.async.cg.shared.global [%0], [%1], 16;" :: "r"(saddr), "l"(gaddr));
}
__device__ __forceinline__ void cp_async_wait_all() {
    asm volatile("cp.async.commit_group;\ncp.async.wait_group 0;" ::: "memory");
}

// ---------------- ranking structure ----------------
__global__ void k_zero_bitmap() {
    int i = blockIdx.x * blockDim.x + threadIdx.x;
    if (i < NWORDS) g_bitmap[i] = 0u;
}

__global__ void k_setbits(const int* __restrict__ labels,
                          const int* __restrict__ uneg) {
    int i = blockIdx.x * blockDim.x + threadIdx.x;
    if (i >= UNZ) return;
    int v = clampv(i < BS ? labels[i] : uneg[i - BS]);
    atomicOr(&g_bitmap[v >> 5], 1u << (v & 31));
}

__global__ void k_blocksums() {
    __shared__ int red[8];
    int base = blockIdx.x * 1024 + threadIdx.x * 4;
    int s = 0;
#pragma unroll
    for (int j = 0; j < 4; j++) {
        int w = base + j;
        if (w < NWORDS) s += __popc(g_bitmap[w]);
    }
    for (int o = 16; o; o >>= 1) s += __shfl_down_sync(0xffffffffu, s, o);
    if ((threadIdx.x & 31) == 0) red[threadIdx.x >> 5] = s;
    __syncthreads();
    if (threadIdx.x == 0) {
        int t = 0;
        for (int w = 0; w < 8; w++) t += red[w];
        g_bsum[blockIdx.x] = t;
    }
}

// wordpref with the 56-element block-prefix folded in (parallel loads, no serial chain)
__global__ void k_wordpref() {
    __shared__ int warpsum[8];
    __shared__ int basesum[2];
    int t = threadIdx.x;
    // block base: sum of g_bsum[0 .. blockIdx.x-1], computed by first 2 warps
    if (t < 64) {
        int idx = t;
        int v = (idx < NSCANBLK && idx < blockIdx.x) ? g_bsum[idx] : 0;
        for (int o = 16; o; o >>= 1) v += __shfl_down_sync(0xffffffffu, v, o);
        if ((t & 31) == 0) basesum[t >> 5] = v;
    }
    int base = blockIdx.x * 1024 + t * 4;
    int c[4]; int s = 0;
#pragma unroll
    for (int j = 0; j < 4; j++) {
        int w = base + j;
        c[j] = (w < NWORDS) ? __popc(g_bitmap[w]) : 0;
        s += c[j];
    }
    int lane = t & 31, wid = t >> 5;
    int incl = s;
    for (int o = 1; o < 32; o <<= 1) {
        int x = __shfl_up_sync(0xffffffffu, incl, o);
        if (lane >= o) incl += x;
    }
    if (lane == 31) warpsum[wid] = incl;
    __syncthreads();
    if (wid == 0 && lane < 8) {
        int v = warpsum[lane];
        int iv = v;
        for (int o = 1; o < 8; o <<= 1) {
            int x = __shfl_up_sync(0xffu, iv, o);
            if (lane >= o) iv += x;
        }
        warpsum[lane] = iv - v;
    }
    __syncthreads();
    int start = basesum[0] + basesum[1] + warpsum[wid] + (incl - s);
#pragma unroll
    for (int j = 0; j < 4; j++) {
        int w = base + j;
        if (w < NWORDS) g_wordpref[w] = start;
        start += c[j];
    }
}

__device__ __forceinline__ int rank_of(int v) {
    unsigned int w = g_bitmap[v >> 5];
    return g_wordpref[v >> 5] + __popc(w & ((1u << (v & 31)) - 1u));
}

__global__ void k_scatter(const int* __restrict__ labels,
                          const int* __restrict__ uneg,
                          const float* __restrict__ probs,
                          const float* __restrict__ temp,
                          const float* __restrict__ icf) {
    int i = blockIdx.x * blockDim.x + threadIdx.x;
    if (i >= UNZ) return;
    int v = clampv(i < BS ? labels[i] : uneg[i - BS]);
    int r = rank_of(v);
    if (r < 0) r = 0;
    if (r >= UNZ) r = UNZ - 1;
    g_sorted[r] = v;
    if (i < BS) g_posidx[i] = r;
    g_bias[r] = (-icf[0] * logf(probs[v] + 1e-11f)) / temp[0];
}

// ---------------- bf16 prep (fused) ----------------
__device__ __forceinline__ uint32_t pack_bf16x2(float lo, float hi) {
    uint32_t l = (uint32_t)__bfloat16_as_ushort(__float2bfloat16_rn(lo));
    uint32_t h = (uint32_t)__bfloat16_as_ushort(__float2bfloat16_rn(hi));
    return (h << 16) | l;
}

// blocks [0, 512): convert x -> bf16;  blocks [512, 3072): gather sorted emb rows
__global__ void k_prep(const float* __restrict__ x, const float* __restrict__ emb) {
    if (blockIdx.x < 512) {
        int i4 = blockIdx.x * 256 + threadIdx.x;      // BS*D/4 = 131072
        float4 v = ((const float4*)x)[i4];
        uint2 o;
        o.x = pack_bf16x2(v.x, v.y);
        o.y = pack_bf16x2(v.z, v.w);
        ((uint2*)g_Xb)[i4] = o;
    } else {
        int row = (blockIdx.x - 512) * 8 + (threadIdx.x >> 5);
        int lane = threadIdx.x & 31;
        int v = g_sorted[row];
        float4 f = ((const float4*)(emb + (size_t)v * D))[lane];
        uint2 o;
        o.x = pack_bf16x2(f.x, f.y);
        o.y = pack_bf16x2(f.z, f.w);
        ((uint2*)g_Ebs)[(size_t)row * 32 + lane] = o;
    }
}

// ---------------- HMMA GEMM + fused epilogue ----------------
#define ROWB   272
#define A_OFF  0
#define B_OFF  (128 * ROWB)
#define EPI_STRIDE 132
#define BIAS_OFF (2 * 128 * ROWB)        // 69632
#define POS_OFF  (BIAS_OFF + 512)
#define SMEM_TOT (POS_OFF + 512)

__device__ __forceinline__ void ldsm_x4(uint32_t addr, uint32_t& r0, uint32_t& r1,
                                        uint32_t& r2, uint32_t& r3) {
    asm volatile("ldmatrix.sync.aligned.m8n8.x4.shared.b16 {%0,%1,%2,%3}, [%4];"
                 : "=r"(r0), "=r"(r1), "=r"(r2), "=r"(r3) : "r"(addr));
}

__device__ __forceinline__ void mma16816(float* c, uint32_t a0, uint32_t a1,
                                         uint32_t a2, uint32_t a3,
                                         uint32_t b0, uint32_t b1) {
    asm volatile("mma.sync.aligned.m16n8k16.row.col.f32.bf16.bf16.f32 "
                 "{%0,%1,%2,%3}, {%4,%5,%6,%7}, {%8,%9}, {%0,%1,%2,%3};"
                 : "+f"(c[0]), "+f"(c[1]), "+f"(c[2]), "+f"(c[3])
                 : "r"(a0), "r"(a1), "r"(a2), "r"(a3), "r"(b0), "r"(b1));
}

__global__ __launch_bounds__(256) void k_gemm_mma(float* __restrict__ out,
                                                  const float* __restrict__ temp) {
    extern __shared__ char sm[];
    uint32_t smb = smem_u32(sm);
    int tid = threadIdx.x;
    int w = tid >> 5, lane = tid & 31;
    int wm = w >> 2, wn = w & 3;
    int N0 = blockIdx.x * 128;
    int M0 = blockIdx.y * 128;

    // ---- stage A, B tiles via cp.async ----
    const uint4* Asrc = (const uint4*)g_Xb;
    const uint4* Bsrc = (const uint4*)g_Ebs;
#pragma unroll
    for (int it = 0; it < 8; it++) {
        int id = tid + it * 256;
        int row = id >> 4, q = id & 15;
        cp_async16(smb + A_OFF + row * ROWB + q * 16, Asrc + (size_t)(M0 + row) * 16 + q);
        cp_async16(smb + B_OFF + row * ROWB + q * 16, Bsrc + (size_t)(N0 + row) * 16 + q);
    }
    if (tid < 128) ((float*)(sm + BIAS_OFF))[tid] = g_bias[N0 + tid];
    else ((int*)(sm + POS_OFF))[tid - 128] = g_posidx[M0 + tid - 128];
    cp_async_wait_all();
    __syncthreads();

    float acc[4][4][4];
#pragma unroll
    for (int i = 0; i < 4; i++)
#pragma unroll
        for (int j = 0; j < 4; j++)
#pragma unroll
            for (int e = 0; e < 4; e++) acc[i][j][e] = 0.f;

    int sel = lane >> 3, r8 = lane & 7;
    uint32_t a_base = smb + A_OFF + (uint32_t)(wm * 64 + (sel & 1) * 8 + r8) * ROWB
                    + (uint32_t)((sel >> 1) * 16);
    uint32_t b_base = smb + B_OFF + (uint32_t)(wn * 32 + (sel >> 1) * 8 + r8) * ROWB
                    + (uint32_t)((sel & 1) * 16);

#pragma unroll
    for (int kk = 0; kk < 8; kk++) {
        uint32_t a[4][4];
#pragma unroll
        for (int mi = 0; mi < 4; mi++)
            ldsm_x4(a_base + (uint32_t)(mi * 16) * ROWB + kk * 32,
                    a[mi][0], a[mi][1], a[mi][2], a[mi][3]);
        uint32_t b[4][2];
#pragma unroll
        for (int p = 0; p < 2; p++) {
            uint32_t r0, r1, r2, r3;
            ldsm_x4(b_base + (uint32_t)(p * 16) * ROWB + kk * 32, r0, r1, r2, r3);
            b[p * 2][0] = r0; b[p * 2][1] = r1;
            b[p * 2 + 1][0] = r2; b[p * 2 + 1][1] = r3;
        }
#pragma unroll
        for (int mi = 0; mi < 4; mi++)
#pragma unroll
            for (int nt = 0; nt < 4; nt++)
                mma16816(acc[mi][nt], a[mi][0], a[mi][1], a[mi][2], a[mi][3],
                         b[nt][0], b[nt][1]);
    }
    __syncthreads();

    // ---- fragments -> smem (fp32, stride 132) ----
    float* epi = (float*)sm;
    int fr = lane >> 2, fc = (lane & 3) * 2;
#pragma unroll
    for (int mi = 0; mi < 4; mi++) {
#pragma unroll
        for (int nt = 0; nt < 4; nt++) {
            int r0 = wm * 64 + mi * 16 + fr;
            int c0 = wn * 32 + nt * 8 + fc;
            *(float2*)&epi[r0 * EPI_STRIDE + c0] = make_float2(acc[mi][nt][0], acc[mi][nt][1]);
            *(float2*)&epi[(r0 + 8) * EPI_STRIDE + c0] = make_float2(acc[mi][nt][2], acc[mi][nt][3]);
        }
    }
    __syncthreads();

    // ---- coalesced epilogue: bias + /temp + positive-column permutation ----
    const float* sbias = (const float*)(sm + BIAS_OFF);
    const int*   spos  = (const int*)(sm + POS_OFF);
    float invt = 1.0f / temp[0];
    int col = tid & 127;
    int rhalf = tid >> 7;
    int c = N0 + col;
    float bc = sbias[col];
#pragma unroll 4
    for (int it = 0; it < 64; it++) {
        int row = it * 2 + rhalf;
        float val = fmaf(epi[row * EPI_STRIDE + col], invt, bc);
        int pr = spos[row];
        int dest = (c == pr) ? 0 : (c < pr ? c + 1 : c);
        stcs(&out[(size_t)(M0 + row) * UNZ + dest], val);
    }
}

// mask: scatter zeros for item_seq hits (excluding the positive column)
__global__ void k_mask(const int* __restrict__ item_seq,
                       float* __restrict__ out) {
    int i = blockIdx.x * blockDim.x + threadIdx.x;
    if (i >= BS * SEQ) return;
    int b = i / SEQ;
    int tkn = item_seq[i];
    if (tkn < 0 || tkn >= VOCAB) return;
    unsigned int w = g_bitmap[tkn >> 5];
    if (!(w & (1u << (tkn & 31)))) return;
    int c = g_wordpref[tkn >> 5] + __popc(w & ((1u << (tkn & 31)) - 1u));
    int pos = g_posidx[b];
    if (c == pos) return;
    int dest = (c < pos) ? c + 1 : c;
    out[(size_t)b * UNZ + dest] = 0.0f;
}

__global__ void k_zerotail(float* out, size_t start, size_t n) {
    size_t i = (size_t)blockIdx.x * blockDim.x + threadIdx.x;
    if (i < n) out[start + i] = 0.f;
}

// ---------------- launch ----------------
extern "C" void kernel_launch(void* const* d_in, const int* in_sizes, int n_in,
                              void* d_out, int out_size) {
    const float* x      = (const float*)d_in[0];
    const int*   labels = (const int*)d_in[1];
    const int*   iseq   = (const int*)d_in[2];
    const float* probs  = (const float*)d_in[3];
    const int*   uneg   = (const int*)d_in[4];
    const float* emb    = (const float*)d_in[5];
    const float* temp   = (const float*)d_in[6];
    const float* icf    = (const float*)d_in[7];
    float* out = (float*)d_out;

    cudaFuncSetAttribute(k_gemm_mma, cudaFuncAttributeMaxDynamicSharedMemorySize, SMEM_TOT);

    k_zero_bitmap<<<(NWORDS + 255) / 256, 256>>>();
    k_setbits<<<(UNZ + 255) / 256, 256>>>(labels, uneg);
    k_blocksums<<<NSCANBLK, 256>>>();
    k_wordpref<<<NSCANBLK, 256>>>();
    k_scatter<<<(UNZ + 255) / 256, 256>>>(labels, uneg, probs, temp, icf);
    k_prep<<<512 + UNZ / 8, 256>>>(x, emb);

    dim3 gg(UNZ / 128, BS / 128);
    k_gemm_mma<<<gg, 256, SMEM_TOT>>>(out, temp);

    k_mask<<<(BS * SEQ + 255) / 256, 256>>>(iseq, out);

    size_t main_n = (size_t)BS * UNZ;
    if ((size_t)out_size > main_n) {
        size_t tail = (size_t)out_size - main_n;
        k_zerotail<<<(unsigned)((tail + 255) / 256), 256>>>(out, main_n, tail);
    }
}